// round 1
// baseline (speedup 1.0000x reference)
#include <cuda_runtime.h>
#include <math.h>

#define BDIM 256
#define LDIM 8192
#define EDIM 64
#define NP   2731      // number of patch-start candidates (multiples of 3): ceil(8192/3)
#define CH   86        // chunk size in p-units (32 chunks cover 2731)
#define NCHUNK 32
#define NTHREADS 256

struct SmemLayout {
    float w2s[EDIM * EDIM];       // 16384 B
    float ent[LDIM];              // 32768 B
    unsigned short cs[LDIM + 2];  // prefix sums (exclusive), cs[0..8192]
    unsigned char xs[LDIM];       // token bytes
    unsigned char nxt[NP + 8];    // step in p-units (1 or 4)
    float term[160];              // entropy LUT term[t*16 + c]
    int hist3[13];
    int hist12[49];
    int wscan[8];
    unsigned char exits[NCHUNK * 4];
    unsigned char esel[NCHUNK];
    int tailS, tailLen, Nv;
    float hsum[EDIM];
};

__global__ void __launch_bounds__(NTHREADS)
ep_kernel(const int* __restrict__ x,
          const float* __restrict__ w1,
          const float* __restrict__ b1,
          const float* __restrict__ w2,
          const float* __restrict__ b2,
          float* __restrict__ out)
{
    extern __shared__ unsigned char raw[];
    SmemLayout* sm = (SmemLayout*)raw;
    const int tid = threadIdx.x;
    const int row = blockIdx.x;
    const int* xr = x + row * LDIM;

    // ---- stage inputs ----
    for (int i = tid; i < EDIM * EDIM; i += NTHREADS) sm->w2s[i] = w2[i];
    for (int i = tid; i < LDIM; i += NTHREADS) sm->xs[i] = (unsigned char)xr[i];
    // entropy LUT: term[t*16+c] = -(c/t)*log2(c/t + 1e-12)
    if (tid < 160) {
        int t = tid >> 4, c = tid & 15;
        float v = 0.0f;
        if (t >= 1 && c <= t) {
            float p = (float)c / (float)t;
            v = -(p * log2f(p + 1e-12f));
        }
        sm->term[tid] = v;
    }
    if (tid == 0) { sm->tailLen = 0; sm->tailS = 0; sm->Nv = 0; }
    if (tid < 13) sm->hist3[tid] = 0;
    if (tid < 49) sm->hist12[tid] = 0;
    __syncthreads();

    // ---- prefix sums (exclusive) into uint16 ----
    const int p0 = tid * 32;
    int local = 0;
    #pragma unroll
    for (int k = 0; k < 32; k++) local += sm->xs[p0 + k];
    // block scan of 256 partials
    {
        int lane = tid & 31, wid = tid >> 5;
        int v = local;
        #pragma unroll
        for (int d = 1; d < 32; d <<= 1) {
            int n = __shfl_up_sync(0xffffffffu, v, d);
            if (lane >= d) v += n;
        }
        if (lane == 31) sm->wscan[wid] = v;
        __syncthreads();
        if (tid < 8) {
            int wv = sm->wscan[tid];
            #pragma unroll
            for (int d = 1; d < 8; d <<= 1) {
                int n = __shfl_up_sync(0x000000ffu, wv, d);
                if (tid >= d) wv += n;
            }
            sm->wscan[tid] = wv;  // inclusive warp totals
        }
        __syncthreads();
        int base = v - local + ((wid > 0) ? sm->wscan[wid - 1] : 0);
        if (tid == 0) sm->cs[0] = 0;
        int run = base;
        #pragma unroll
        for (int k = 0; k < 32; k++) {
            run += sm->xs[p0 + k];
            sm->cs[p0 + k + 1] = (unsigned short)run;
        }
    }

    // ---- entropy: packed 4-bit counts, sliding window of 9 ----
    {
        unsigned int packed = 0;
        int lo = p0 - 4; if (lo < 0) lo = 0;
        int hi = p0 + 4; if (hi > LDIM - 1) hi = LDIM - 1;
        for (int m = lo; m <= hi; m++) packed += 1u << (sm->xs[m] << 2);

        #pragma unroll 4
        for (int k = 0; k < 32; k++) {
            int p = p0 + k;
            int wl = p - 4; if (wl < 0) wl = 0;
            int wh = p + 4; if (wh > LDIM - 1) wh = LDIM - 1;
            int t = wh - wl + 1;
            const float* tb = &sm->term[t << 4];
            unsigned int pk = packed;
            float ent;
            ent  = tb[pk & 15]; pk >>= 4;
            ent += tb[pk & 15]; pk >>= 4;
            ent += tb[pk & 15]; pk >>= 4;
            ent += tb[pk & 15]; pk >>= 4;
            ent += tb[pk & 15];
            sm->ent[p] = ent;
            if (p % 3 == 0) sm->nxt[p / 3] = (ent > 1.5f) ? (unsigned char)1 : (unsigned char)4;
            // slide to p+1: add token at p+5, remove at p-4
            int ap = p + 5;
            if (ap < LDIM) packed += 1u << (sm->xs[ap] << 2);
            int rp = p - 4;
            if (rp >= 0) packed -= 1u << (sm->xs[rp] << 2);
        }
    }
    __syncthreads();

    // ---- phase B: speculative chunk walks (128 threads) || entropy copy-out (128 threads) ----
    if (tid < NCHUNK * 4) {
        int chunk = tid >> 2, e = tid & 3;
        int p = chunk * CH + e;
        int pend = (chunk + 1) * CH; if (pend > NP) pend = NP;
        while (p < pend) p += sm->nxt[p];
        sm->exits[tid] = (unsigned char)(p - pend);
    } else {
        float* outE = out + (size_t)BDIM * EDIM + (size_t)row * LDIM;
        for (int i = tid - 128; i < LDIM; i += 128) outE[i] = sm->ent[i];
    }
    __syncthreads();

    // ---- phase B': compose entry offsets across chunks ----
    if (tid == 0) {
        unsigned char e = 0;
        sm->esel[0] = 0;
        #pragma unroll 1
        for (int c = 0; c < NCHUNK - 1; c++) {
            e = sm->exits[c * 4 + e];
            sm->esel[c + 1] = e;
        }
    }
    __syncthreads();

    // ---- phase C: real walk per chunk, histogram of patch sums ----
    if (tid < NCHUNK) {
        int p = tid * CH + sm->esel[tid];
        int pend = (tid + 1) * CH; if (pend > NP) pend = NP;
        int nv = 0;
        while (p < pend) {
            int u = (int)sm->nxt[p];
            int i3 = 3 * p;
            int j = i3 + 3 * u; if (j > LDIM) j = LDIM;
            int len = j - i3;
            int S = (int)sm->cs[j] - (int)sm->cs[i3];
            nv++;
            if (len == 3)       atomicAdd(&sm->hist3[S], 1);
            else if (len == 12) atomicAdd(&sm->hist12[S], 1);
            else { sm->tailS = S; sm->tailLen = len; }  // unique tail patch
            p += u;
        }
        atomicAdd(&sm->Nv, nv);
    }
    __syncthreads();

    // ---- phase D: hsum[e] = mean over valid patches of relu(mean*w1[e]+b1[e]) ----
    if (tid < EDIM) {
        float w1e = w1[tid], b1e = b1[tid];
        float acc = 0.0f;
        #pragma unroll
        for (int s = 0; s <= 12; s++) {
            float h = fmaxf(fmaf((float)s / 3.0f, w1e, b1e), 0.0f);
            acc += (float)sm->hist3[s] * h;
        }
        #pragma unroll
        for (int s = 0; s <= 48; s++) {
            float h = fmaxf(fmaf((float)s / 12.0f, w1e, b1e), 0.0f);
            acc += (float)sm->hist12[s] * h;
        }
        if (sm->tailLen > 0) {
            float m = (float)sm->tailS / (float)sm->tailLen;
            acc += fmaxf(fmaf(m, w1e, b1e), 0.0f);
        }
        sm->hsum[tid] = acc / (float)sm->Nv;
    }
    __syncthreads();

    // ---- phase E: vec = hbar @ w2^T + b2 ----
    if (tid < EDIM) {
        float v = b2[tid];
        const float* wrow = &sm->w2s[tid * EDIM];
        #pragma unroll
        for (int e = 0; e < EDIM; e++) v = fmaf(sm->hsum[e], wrow[e], v);
        out[(size_t)row * EDIM + tid] = v;
    }
}

extern "C" void kernel_launch(void* const* d_in, const int* in_sizes, int n_in,
                              void* d_out, int out_size)
{
    const int*   x  = (const int*)d_in[0];
    const float* w1 = (const float*)d_in[1];
    const float* b1 = (const float*)d_in[2];
    const float* w2 = (const float*)d_in[3];
    const float* b2 = (const float*)d_in[4];
    float* out = (float*)d_out;

    cudaFuncSetAttribute(ep_kernel, cudaFuncAttributeMaxDynamicSharedMemorySize,
                         (int)sizeof(SmemLayout));
    ep_kernel<<<BDIM, NTHREADS, sizeof(SmemLayout)>>>(x, w1, b1, w2, b2, out);
}

// round 2
// speedup vs baseline: 1.1991x; 1.1991x over previous
#include <cuda_runtime.h>
#include <math.h>

#define BDIM 256
#define LDIM 8192
#define EDIM 64
#define NP   2731      // patch-start candidates (multiples of 3): ceil(8192/3)
#define CH   86        // chunk size in p-units (32 chunks cover 2731)
#define NCHUNK 32
#define NTHREADS 256

struct SmemLayout {
    float ent[8448];                 // entropy, padded 32->33; later reused as w2s[64*65]
    unsigned short cs[8708];         // prefix sums, padded 32->34
    unsigned char xs[9216];          // token bytes, padded 32->36
    unsigned char nxt[NP + 8];       // step in p-units (1 or 4)
    unsigned char nxt2[NP + 8];      // squared step
    float term[160];                 // generic entropy LUT term[t*16+c]
    float term9[320];                // t=9 LUT replicated per lane: [c*32+lane]
    unsigned int exitsW[NCHUNK];     // 4 exit bytes per chunk
    unsigned char esel[NCHUNK];
    int hist3[13];
    int hist12[49];
    int wscan[8];
    int tailS, tailLen, Nv;
    float hsum[EDIM];
};

__device__ __forceinline__ int xsi(int p) { return p + ((p >> 5) << 2); }
__device__ __forceinline__ int csi(int i) { return i + ((i >> 5) << 1); }
__device__ __forceinline__ int eni(int p) { return p + (p >> 5); }

__global__ void __launch_bounds__(NTHREADS)
ep_kernel(const int* __restrict__ x,
          const float* __restrict__ w1,
          const float* __restrict__ b1,
          const float* __restrict__ w2,
          const float* __restrict__ b2,
          float* __restrict__ out)
{
    extern __shared__ unsigned char raw[];
    SmemLayout* sm = (SmemLayout*)raw;
    const int tid = threadIdx.x;
    const int lane = tid & 31;
    const int row = blockIdx.x;
    const int p0 = tid * 32;

    // ---- stage own 32 tokens into registers (8 x int4), mirror bytes to padded xs ----
    const int4* xv = (const int4*)(x + (size_t)row * LDIM) + tid * 8;
    unsigned int tw[8];
    int localSum = 0;
    #pragma unroll
    for (int k = 0; k < 8; k++) {
        int4 v = xv[k];
        unsigned int w = (unsigned int)v.x | ((unsigned int)v.y << 8) |
                         ((unsigned int)v.z << 16) | ((unsigned int)v.w << 24);
        tw[k] = w;
        localSum += v.x + v.y + v.z + v.w;
        *(unsigned int*)(sm->xs + tid * 36 + 4 * k) = w;   // conflict-free (36B lane stride)
    }

    // ---- LUTs & init ----
    if (tid < 160) {
        int t = tid >> 4, c = tid & 15;
        float v = 0.0f;
        if (t >= 1 && c <= t) { float pv = (float)c / (float)t; v = -(pv * log2f(pv + 1e-12f)); }
        sm->term[tid] = v;
    }
    for (int i = tid; i < 320; i += NTHREADS) {
        int c = i >> 5;
        float v = 0.0f;
        if (c <= 9) { float pv = (float)c / (float)9; v = -(pv * log2f(pv + 1e-12f)); }
        sm->term9[i] = v;
    }
    if (tid < 13) sm->hist3[tid] = 0;
    if (tid < 49) sm->hist12[tid] = 0;
    if (tid == 0) { sm->tailLen = 0; sm->tailS = 0; sm->Nv = 0; }

    // ---- block scan of localSum; write padded cs from registers ----
    {
        int wid = tid >> 5;
        int v = localSum;
        #pragma unroll
        for (int d = 1; d < 32; d <<= 1) {
            int n = __shfl_up_sync(0xffffffffu, v, d);
            if (lane >= d) v += n;
        }
        if (lane == 31) sm->wscan[wid] = v;
        __syncthreads();
        if (tid < 8) {
            int wv = sm->wscan[tid];
            #pragma unroll
            for (int d = 1; d < 8; d <<= 1) {
                int n = __shfl_up_sync(0xffu, wv, d);
                if (tid >= d) wv += n;
            }
            sm->wscan[tid] = wv;
        }
        __syncthreads();
        int base = v - localSum + ((wid > 0) ? sm->wscan[wid - 1] : 0);
        if (tid == 0) sm->cs[0] = 0;
        int run = base;
        #pragma unroll
        for (int k = 0; k < 32; k++) {
            run += (int)((tw[k >> 2] >> ((k & 3) * 8)) & 0xFF);
            sm->cs[csi(p0 + k + 1)] = (unsigned short)run;   // conflict-free (34-short stride)
        }
    }

    // ---- entropy: packed 4-bit counts, sliding window of 9, registers + per-lane LUT ----
    {
        const bool firstT = (tid == 0);
        const bool lastT = (tid == NTHREADS - 1);
        unsigned int pm = 0, ep = 0, ep4 = 0;
        if (!firstT) pm = *(const unsigned int*)(sm->xs + tid * 36 - 8);      // tokens p0-4..p0-1
        if (!lastT) {
            ep  = *(const unsigned int*)(sm->xs + (tid + 1) * 36);            // tokens p0+32..p0+35
            ep4 = sm->xs[(tid + 1) * 36 + 4];                                 // token p0+36
        }

        auto tok = [&](int idx) -> unsigned int {
            if (idx < 0)       return (pm >> ((idx + 4) * 8)) & 0xFF;
            else if (idx < 32) return (tw[idx >> 2] >> ((idx & 3) * 8)) & 0xFF;
            else if (idx < 36) return (ep >> ((idx - 32) * 8)) & 0xFF;
            else               return ep4;
        };

        unsigned int packed = 0;
        #pragma unroll
        for (int i = 0; i <= 4; i++) packed += 1u << (tok(i) << 2);
        if (!firstT) {
            #pragma unroll
            for (int i = -4; i < 0; i++) packed += 1u << (tok(i) << 2);
        }

        int r0 = (3 - (p0 % 3)) % 3;       // first k with (p0+k)%3==0
        int q = (p0 + r0) / 3;
        float* entb = sm->ent + tid * 33;  // conflict-free (33-float stride)
        const float* t9 = sm->term9 + lane;

        #pragma unroll
        for (int k = 0; k < 32; k++) {
            int p = p0 + k;
            float e;
            if ((firstT && k < 4) || (lastT && k >= 28)) {
                int wl = max(0, p - 4), wh = min(LDIM - 1, p + 4);
                int t = wh - wl + 1;
                const float* tb = sm->term + (t << 4);
                unsigned int pk = packed;
                e  = tb[pk & 15]; pk >>= 4;
                e += tb[pk & 15]; pk >>= 4;
                e += tb[pk & 15]; pk >>= 4;
                e += tb[pk & 15]; pk >>= 4;
                e += tb[pk & 15];
            } else {
                unsigned int pk = packed;
                e  = t9[(pk & 15) << 5]; pk >>= 4;
                e += t9[(pk & 15) << 5]; pk >>= 4;
                e += t9[(pk & 15) << 5]; pk >>= 4;
                e += t9[(pk & 15) << 5]; pk >>= 4;
                e += t9[(pk & 15) << 5];
            }
            entb[k] = e;
            if ((k % 3) == r0) { sm->nxt[q] = (e > 1.5f) ? (unsigned char)1 : (unsigned char)4; q++; }
            if (!(lastT && k >= 27)) packed += 1u << (tok(k + 5) << 2);
            if (!(firstT && k < 4))  packed -= 1u << (tok(k - 4) << 2);
        }
    }
    __syncthreads();

    // ---- squared step table ----
    for (int p = tid; p < NP; p += NTHREADS) {
        int u = sm->nxt[p];
        int qq = p + u;
        sm->nxt2[p] = (unsigned char)(u + ((qq < NP) ? (int)sm->nxt[qq] : 4));
    }
    __syncthreads();

    // ---- speculative chunk walks (43-step chains) || entropy copy-out ----
    if (tid < NCHUNK * 4) {
        int chunk = tid >> 2, e = tid & 3;
        int p = chunk * CH + e;
        int pend = min((chunk + 1) * CH, NP);
        while (p < pend) {
            int u1 = sm->nxt[p];
            int p1 = p + u1;
            if (p1 >= pend) { p = p1; break; }
            p += (int)sm->nxt2[p];
        }
        ((unsigned char*)sm->exitsW)[tid] = (unsigned char)(p - pend);
    } else {
        float* outE = out + (size_t)BDIM * EDIM + (size_t)row * LDIM;
        for (int i = tid - 128; i < LDIM; i += 128) outE[i] = sm->ent[eni(i)];
    }
    __syncthreads();

    // ---- compose entry offsets: warp shuffle-scan with byte_perm map composition ----
    if (tid < 32) {
        unsigned int m = sm->exitsW[tid];
        #pragma unroll
        for (int d = 1; d < 32; d <<= 1) {
            unsigned int pmv = __shfl_up_sync(0xffffffffu, m, d);
            if (lane >= d) {
                unsigned int sel = (pmv & 0x3u) | ((pmv >> 4) & 0x30u) |
                                   ((pmv >> 8) & 0x300u) | ((pmv >> 12) & 0x3000u);
                m = __byte_perm(m, 0, sel);   // m = m_cur ∘ m_prev
            }
        }
        if (tid == 0) sm->esel[0] = 0;
        if (tid < NCHUNK - 1) sm->esel[tid + 1] = (unsigned char)(m & 0xFF);
    }
    __syncthreads();

    // ---- real walk (2 patches / chain step) || stage w2 into freed ent buffer ----
    if (tid < NCHUNK) {
        int p = tid * CH + (int)sm->esel[tid];
        int pend = min((tid + 1) * CH, NP);
        int nv = 0;
        while (p < pend) {
            int u1 = sm->nxt[p];
            int u2 = sm->nxt2[p];
            {
                int i3 = 3 * p;
                int j = min(i3 + 3 * u1, LDIM);
                int len = j - i3;
                int S = (int)sm->cs[csi(j)] - (int)sm->cs[csi(i3)];
                nv++;
                if (len == 3)       atomicAdd(&sm->hist3[S], 1);
                else if (len == 12) atomicAdd(&sm->hist12[S], 1);
                else { sm->tailS = S; sm->tailLen = len; }
            }
            int p1 = p + u1;
            if (p1 < pend) {
                int ul = u2 - u1;
                int i3 = 3 * p1;
                int j = min(i3 + 3 * ul, LDIM);
                int len = j - i3;
                int S = (int)sm->cs[csi(j)] - (int)sm->cs[csi(i3)];
                nv++;
                if (len == 3)       atomicAdd(&sm->hist3[S], 1);
                else if (len == 12) atomicAdd(&sm->hist12[S], 1);
                else { sm->tailS = S; sm->tailLen = len; }
                p += u2;
            } else {
                p = p1;
            }
        }
        atomicAdd(&sm->Nv, nv);
    } else {
        float* w2s = sm->ent;   // ent no longer needed (copy-out done)
        for (int i = tid - 32; i < EDIM * EDIM; i += NTHREADS - 32) {
            int r = i >> 6, c = i & 63;
            w2s[r * 65 + c] = w2[i];   // padded: conflict-free reads in phase E
        }
    }
    __syncthreads();

    // ---- hsum[e] = mean over valid patches of relu(mean*w1[e]+b1[e]) via histogram ----
    if (tid < EDIM) {
        float w1e = w1[tid], b1e = b1[tid];
        float acc = 0.0f;
        #pragma unroll
        for (int s = 0; s <= 12; s++)
            acc += (float)sm->hist3[s] * fmaxf(fmaf((float)s / 3.0f, w1e, b1e), 0.0f);
        #pragma unroll
        for (int s = 0; s <= 48; s++)
            acc += (float)sm->hist12[s] * fmaxf(fmaf((float)s / 12.0f, w1e, b1e), 0.0f);
        if (sm->tailLen > 0)
            acc += fmaxf(fmaf((float)sm->tailS / (float)sm->tailLen, w1e, b1e), 0.0f);
        sm->hsum[tid] = acc / (float)sm->Nv;
    }
    __syncthreads();

    // ---- vec = hbar @ w2^T + b2 ----
    if (tid < EDIM) {
        const float* w2s = sm->ent + tid * 65;
        float v = b2[tid];
        #pragma unroll
        for (int e = 0; e < EDIM; e++) v = fmaf(sm->hsum[e], w2s[e], v);
        out[(size_t)row * EDIM + tid] = v;
    }
}

extern "C" void kernel_launch(void* const* d_in, const int* in_sizes, int n_in,
                              void* d_out, int out_size)
{
    const int*   x  = (const int*)d_in[0];
    const float* w1 = (const float*)d_in[1];
    const float* b1 = (const float*)d_in[2];
    const float* w2 = (const float*)d_in[3];
    const float* b2 = (const float*)d_in[4];
    float* out = (float*)d_out;

    cudaFuncSetAttribute(ep_kernel, cudaFuncAttributeMaxDynamicSharedMemorySize,
                         (int)sizeof(SmemLayout));
    ep_kernel<<<BDIM, NTHREADS, sizeof(SmemLayout)>>>(x, w1, b1, w2, b2, out);
}

// round 3
// speedup vs baseline: 1.9847x; 1.6552x over previous
#include <cuda_runtime.h>
#include <math.h>

#define BDIM 256
#define LDIM 8192
#define EDIM 64
#define NP   2731      // patch-start candidates (multiples of 3): ceil(8192/3)
#define CH   43        // chunk size in p-units (64 chunks cover 2731)
#define NCHUNK 64
#define NTHREADS 256
#define NBINS 68       // 0..12 len3, 16..64 len12, 66 dummy

struct SmemLayout {
    float ent[8448];                 // entropy, padded 32->33
    float w2s[EDIM * 65];            // w2 padded rows
    unsigned short cs[8708];         // prefix sums, padded 32->34
    unsigned char xs[9216];          // token bytes, padded 32->36
    unsigned char nxt[NP + 8];       // step in p-units (1 or 4)
    unsigned char nxt2[NP + 8];      // squared step
    float term[160];                 // generic entropy LUT term[t*16+c]
    float term9[320];                // t=9 LUT replicated per lane
    unsigned int exitsW[NCHUNK];     // 4 exit bytes per chunk
    unsigned char esel[NCHUNK + 4];
    int histW[2][NBINS];             // per-warp histograms (no atomics)
    int NvW[2];
    int wscan[8];
    int tailS, tailLen;
    float hsum[EDIM];
};

__device__ __forceinline__ int csi(int i) { return i + ((i >> 5) << 1); }
__device__ __forceinline__ int eni(int p) { return p + (p >> 5); }

__global__ void __launch_bounds__(NTHREADS, 2)
ep_kernel(const int* __restrict__ x,
          const float* __restrict__ w1,
          const float* __restrict__ b1,
          const float* __restrict__ w2,
          const float* __restrict__ b2,
          float* __restrict__ out)
{
    extern __shared__ unsigned char raw[];
    SmemLayout* sm = (SmemLayout*)raw;
    const int tid = threadIdx.x;
    const int lane = tid & 31;
    const int row = blockIdx.x;
    const int p0 = tid * 32;

    // ---- stage own 32 tokens into registers (8 x int4), mirror bytes to padded xs ----
    const int4* xv = (const int4*)(x + (size_t)row * LDIM) + tid * 8;
    unsigned int tw[8];
    int localSum = 0;
    #pragma unroll
    for (int k = 0; k < 8; k++) {
        int4 v = xv[k];
        unsigned int w = (unsigned int)v.x | ((unsigned int)v.y << 8) |
                         ((unsigned int)v.z << 16) | ((unsigned int)v.w << 24);
        tw[k] = w;
        localSum += v.x + v.y + v.z + v.w;
        *(unsigned int*)(sm->xs + tid * 36 + 4 * k) = w;   // conflict-free (36B lane stride)
    }

    // ---- LUTs & init ----
    if (tid < 160) {
        int t = tid >> 4, c = tid & 15;
        float v = 0.0f;
        if (t >= 1 && c <= t) { float pv = (float)c / (float)t; v = -(pv * log2f(pv + 1e-12f)); }
        sm->term[tid] = v;
    }
    for (int i = tid; i < 320; i += NTHREADS) {
        int c = i >> 5;
        float v = 0.0f;
        if (c <= 9) { float pv = (float)c / (float)9; v = -(pv * log2f(pv + 1e-12f)); }
        sm->term9[i] = v;
    }
    for (int i = tid; i < 2 * NBINS; i += NTHREADS) ((int*)sm->histW)[i] = 0;
    if (tid == 0) { sm->tailLen = 0; sm->tailS = 0; sm->NvW[0] = 0; sm->NvW[1] = 0; }

    // ---- block scan of localSum; write padded cs from registers ----
    {
        int wid = tid >> 5;
        int v = localSum;
        #pragma unroll
        for (int d = 1; d < 32; d <<= 1) {
            int n = __shfl_up_sync(0xffffffffu, v, d);
            if (lane >= d) v += n;
        }
        if (lane == 31) sm->wscan[wid] = v;
        __syncthreads();
        if (tid < 8) {
            int wv = sm->wscan[tid];
            #pragma unroll
            for (int d = 1; d < 8; d <<= 1) {
                int n = __shfl_up_sync(0xffu, wv, d);
                if (tid >= d) wv += n;
            }
            sm->wscan[tid] = wv;
        }
        __syncthreads();
        int base = v - localSum + ((wid > 0) ? sm->wscan[wid - 1] : 0);
        if (tid == 0) sm->cs[0] = 0;
        int run = base;
        #pragma unroll
        for (int k = 0; k < 32; k++) {
            run += (int)((tw[k >> 2] >> ((k & 3) * 8)) & 0xFF);
            sm->cs[csi(p0 + k + 1)] = (unsigned short)run;   // conflict-free (34-short stride)
        }
    }

    // ---- entropy: packed 4-bit counts, sliding window of 9 ----
    {
        const bool firstT = (tid == 0);
        const bool lastT = (tid == NTHREADS - 1);
        unsigned int pm = 0, ep = 0, ep4 = 0;
        if (!firstT) pm = *(const unsigned int*)(sm->xs + tid * 36 - 8);      // p0-4..p0-1
        if (!lastT) {
            ep  = *(const unsigned int*)(sm->xs + (tid + 1) * 36);            // p0+32..p0+35
            ep4 = sm->xs[(tid + 1) * 36 + 4];                                 // p0+36
        }

        auto tok = [&](int idx) -> unsigned int {
            if (idx < 0)       return (pm >> ((idx + 4) * 8)) & 0xFF;
            else if (idx < 32) return (tw[idx >> 2] >> ((idx & 3) * 8)) & 0xFF;
            else if (idx < 36) return (ep >> ((idx - 32) * 8)) & 0xFF;
            else               return ep4;
        };

        unsigned int packed = 0;
        #pragma unroll
        for (int i = 0; i <= 4; i++) packed += 1u << (tok(i) << 2);
        if (!firstT) {
            #pragma unroll
            for (int i = -4; i < 0; i++) packed += 1u << (tok(i) << 2);
        }

        int r0 = (3 - (p0 % 3)) % 3;
        int q = (p0 + r0) / 3;
        float* entb = sm->ent + tid * 33;
        const float* t9 = sm->term9 + lane;

        #pragma unroll
        for (int k = 0; k < 32; k++) {
            int p = p0 + k;
            float e;
            if ((firstT && k < 4) || (lastT && k >= 28)) {
                int wl = max(0, p - 4), wh = min(LDIM - 1, p + 4);
                int t = wh - wl + 1;
                const float* tb = sm->term + (t << 4);
                unsigned int pk = packed;
                e  = tb[pk & 15]; pk >>= 4;
                e += tb[pk & 15]; pk >>= 4;
                e += tb[pk & 15]; pk >>= 4;
                e += tb[pk & 15]; pk >>= 4;
                e += tb[pk & 15];
            } else {
                unsigned int pk = packed;
                e  = t9[(pk & 15) << 5]; pk >>= 4;
                e += t9[(pk & 15) << 5]; pk >>= 4;
                e += t9[(pk & 15) << 5]; pk >>= 4;
                e += t9[(pk & 15) << 5]; pk >>= 4;
                e += t9[(pk & 15) << 5];
            }
            entb[k] = e;
            if ((k % 3) == r0) { sm->nxt[q] = (e > 1.5f) ? (unsigned char)1 : (unsigned char)4; q++; }
            if (!(lastT && k >= 27)) packed += 1u << (tok(k + 5) << 2);
            if (!(firstT && k < 4))  packed -= 1u << (tok(k - 4) << 2);
        }
    }
    __syncthreads();

    // ---- squared step table ----
    for (int p = tid; p < NP; p += NTHREADS) {
        int u = sm->nxt[p];
        int qq = p + u;
        sm->nxt2[p] = (unsigned char)(u + ((qq < NP) ? (int)sm->nxt[qq] : 4));
    }
    __syncthreads();

    // ---- speculative chunk walks: 64 chunks x 4 entries = all 256 threads ----
    {
        int chunk = tid >> 2, e = tid & 3;
        int p = chunk * CH + e;
        int pend = min((chunk + 1) * CH, NP);
        while (p < pend) {
            int u1 = sm->nxt[p];
            int p1 = p + u1;
            if (p1 >= pend) { p = p1; break; }
            p += (int)sm->nxt2[p];
        }
        ((unsigned char*)sm->exitsW)[tid] = (unsigned char)(p - pend);
    }
    __syncthreads();

    // ---- warp 0: compose 64 chunk maps (two shuffle scans) || others: entropy copy-out ----
    if (tid < 32) {
        // first half: chunks 0..31
        unsigned int m = sm->exitsW[lane];
        #pragma unroll
        for (int d = 1; d < 32; d <<= 1) {
            unsigned int pmv = __shfl_up_sync(0xffffffffu, m, d);
            if (lane >= d) {
                unsigned int sel = (pmv & 0x3u) | ((pmv >> 4) & 0x30u) |
                                   ((pmv >> 8) & 0x300u) | ((pmv >> 12) & 0x3000u);
                m = __byte_perm(m, 0, sel);
            }
        }
        if (lane == 0) sm->esel[0] = 0;
        sm->esel[lane + 1] = (unsigned char)(m & 0x3u);      // esel[1..32]
        unsigned int e32 = __shfl_sync(0xffffffffu, m, 31) & 0x3u;
        // second half: chunks 32..63
        unsigned int m2 = sm->exitsW[32 + lane];
        #pragma unroll
        for (int d = 1; d < 32; d <<= 1) {
            unsigned int pmv = __shfl_up_sync(0xffffffffu, m2, d);
            if (lane >= d) {
                unsigned int sel = (pmv & 0x3u) | ((pmv >> 4) & 0x30u) |
                                   ((pmv >> 8) & 0x300u) | ((pmv >> 12) & 0x3000u);
                m2 = __byte_perm(m2, 0, sel);
            }
        }
        if (lane < 31) sm->esel[32 + lane + 1] = (unsigned char)((m2 >> (8 * e32)) & 0x3u);
    } else {
        float* outE = out + (size_t)BDIM * EDIM + (size_t)row * LDIM;
        for (int i = tid - 32; i < LDIM; i += NTHREADS - 32) outE[i] = sm->ent[eni(i)];
    }
    __syncthreads();

    // ---- real walk: 64 threads, fixed trip count, match_any histogram (no atomics) ----
    if (tid < NCHUNK) {
        int p = tid * CH + (int)sm->esel[tid];
        int pend = min((tid + 1) * CH, NP);
        int nv = 0;
        int* hw = sm->histW[tid >> 5];
        #pragma unroll 1
        for (int it = 0; it < 23; it++) {
            int key1 = 66, key2 = 66;
            if (p < pend) {
                int u1 = (int)sm->nxt[p];
                int u2 = (int)sm->nxt2[p];
                {
                    int i3 = 3 * p;
                    int j = min(i3 + 3 * u1, LDIM);
                    int len = j - i3;
                    int S = (int)sm->cs[csi(j)] - (int)sm->cs[csi(i3)];
                    nv++;
                    if (len == 3)       key1 = S;
                    else if (len == 12) key1 = 16 + S;
                    else { sm->tailS = S; sm->tailLen = len; }
                }
                int p1 = p + u1;
                if (p1 < pend) {
                    int ul = u2 - u1;
                    int i3 = 3 * p1;
                    int j = min(i3 + 3 * ul, LDIM);
                    int len = j - i3;
                    int S = (int)sm->cs[csi(j)] - (int)sm->cs[csi(i3)];
                    nv++;
                    if (len == 3)       key2 = S;
                    else if (len == 12) key2 = 16 + S;
                    else { sm->tailS = S; sm->tailLen = len; }
                    p += u2;
                } else {
                    p = p1;
                }
            }
            unsigned int g1 = __match_any_sync(0xffffffffu, key1);
            if (key1 != 66 && (__ffs(g1) - 1) == lane) hw[key1] += __popc(g1);
            unsigned int g2 = __match_any_sync(0xffffffffu, key2);
            if (key2 != 66 && (__ffs(g2) - 1) == lane) hw[key2] += __popc(g2);
        }
        // warp-reduce nv
        #pragma unroll
        for (int d = 16; d > 0; d >>= 1) nv += __shfl_down_sync(0xffffffffu, nv, d);
        if (lane == 0) sm->NvW[tid >> 5] = nv;
    } else {
        // stage w2 into padded smem
        for (int i = tid - NCHUNK; i < EDIM * EDIM; i += NTHREADS - NCHUNK) {
            sm->w2s[(i >> 6) * 65 + (i & 63)] = w2[i];
        }
    }
    __syncthreads();

    // ---- hsum[e] = mean over valid patches of relu(mean*w1[e]+b1[e]) via histogram ----
    if (tid < EDIM) {
        float w1e = w1[tid], b1e = b1[tid];
        float acc = 0.0f;
        #pragma unroll
        for (int s = 0; s <= 12; s++) {
            int c = sm->histW[0][s] + sm->histW[1][s];
            acc += (float)c * fmaxf(fmaf((float)s / 3.0f, w1e, b1e), 0.0f);
        }
        #pragma unroll
        for (int s = 0; s <= 48; s++) {
            int c = sm->histW[0][16 + s] + sm->histW[1][16 + s];
            acc += (float)c * fmaxf(fmaf((float)s / 12.0f, w1e, b1e), 0.0f);
        }
        if (sm->tailLen > 0)
            acc += fmaxf(fmaf((float)sm->tailS / (float)sm->tailLen, w1e, b1e), 0.0f);
        sm->hsum[tid] = acc / (float)(sm->NvW[0] + sm->NvW[1]);
    }
    __syncthreads();

    // ---- vec = hbar @ w2^T + b2 ----
    if (tid < EDIM) {
        const float* wrow = sm->w2s + tid * 65;
        float v = b2[tid];
        #pragma unroll
        for (int e = 0; e < EDIM; e++) v = fmaf(sm->hsum[e], wrow[e], v);
        out[(size_t)row * EDIM + tid] = v;
    }
}

extern "C" void kernel_launch(void* const* d_in, const int* in_sizes, int n_in,
                              void* d_out, int out_size)
{
    const int*   x  = (const int*)d_in[0];
    const float* w1 = (const float*)d_in[1];
    const float* b1 = (const float*)d_in[2];
    const float* w2 = (const float*)d_in[3];
    const float* b2 = (const float*)d_in[4];
    float* out = (float*)d_out;

    cudaFuncSetAttribute(ep_kernel, cudaFuncAttributeMaxDynamicSharedMemorySize,
                         (int)sizeof(SmemLayout));
    ep_kernel<<<BDIM, NTHREADS, sizeof(SmemLayout)>>>(x, w1, b1, w2, b2, out);
}

// round 4
// speedup vs baseline: 2.5392x; 1.2794x over previous
#include <cuda_runtime.h>
#include <math.h>

#define BDIM 256
#define LDIM 8192
#define EDIM 64
#define NP   2731      // patch-start candidates (multiples of 3): ceil(8192/3)
#define CH   22        // chunk size in p-units (128 chunks cover 2731)
#define NCHUNK 128
#define NTHREADS 512
#define TPT 16         // tokens per thread
#define NBINS 68       // 0..12 len3, 16..64 len12, 66 dummy
#define NWALKW 4       // warps doing the real walk

struct SmemLayout {
    float ent[8704];                 // entropy, padded 16->17 floats per thread
    float w2s[EDIM * 65];            // w2 padded rows
    unsigned short cs[9232];         // prefix sums, padded 16->18 shorts per thread
    unsigned char xs[10240];         // token bytes, padded 16->20 per thread
    unsigned char nxt[NP + 8];       // step in p-units (1 or 4)
    unsigned char nxt2[NP + 8];      // squared step
    float term[160];                 // generic entropy LUT term[t*16+c]
    float term9[320];                // t=9 LUT replicated per lane
    unsigned int exitsW[NCHUNK];     // 4 exit bytes per chunk
    unsigned int mfull[NCHUNK];      // per-chunk prefix-composed maps (within warp)
    unsigned char wtotE[8];          // composed warp-entry offsets E[0..4]
    unsigned char esel[NCHUNK + 4];
    int histW[NWALKW][NBINS];        // per-warp histograms (no atomics)
    int NvW[NWALKW];
    int wscan[16];
    int tailS, tailLen;
    float hsum[EDIM];
};

__device__ __forceinline__ int csi(int i) { return i + ((i >> 4) << 1); }
__device__ __forceinline__ int eni(int p) { return p + (p >> 4); }

__global__ void __launch_bounds__(NTHREADS, 2)
ep_kernel(const int* __restrict__ x,
          const float* __restrict__ w1,
          const float* __restrict__ b1,
          const float* __restrict__ w2,
          const float* __restrict__ b2,
          float* __restrict__ out)
{
    extern __shared__ unsigned char raw[];
    SmemLayout* sm = (SmemLayout*)raw;
    const int tid = threadIdx.x;
    const int lane = tid & 31;
    const int wid = tid >> 5;
    const int row = blockIdx.x;
    const int p0 = tid * TPT;

    // ---- stage own 16 tokens into registers (4 x int4), mirror bytes to padded xs ----
    const int4* xv = (const int4*)(x + (size_t)row * LDIM) + tid * 4;
    unsigned int tw[4];
    int localSum = 0;
    #pragma unroll
    for (int k = 0; k < 4; k++) {
        int4 v = xv[k];
        unsigned int w = (unsigned int)v.x | ((unsigned int)v.y << 8) |
                         ((unsigned int)v.z << 16) | ((unsigned int)v.w << 24);
        tw[k] = w;
        localSum += v.x + v.y + v.z + v.w;
        *(unsigned int*)(sm->xs + tid * 20 + 4 * k) = w;   // 20B stride: conflict-free
    }

    // ---- LUTs & init ----
    if (tid < 160) {
        int t = tid >> 4, c = tid & 15;
        float v = 0.0f;
        if (t >= 1 && c <= t) { float pv = (float)c / (float)t; v = -(pv * log2f(pv + 1e-12f)); }
        sm->term[tid] = v;
    }
    if (tid >= 160 && tid < 480) {
        int i = tid - 160;
        int c = i >> 5;
        float v = 0.0f;
        if (c <= 9) { float pv = (float)c / 9.0f; v = -(pv * log2f(pv + 1e-12f)); }
        sm->term9[i] = v;
    }
    for (int i = tid; i < NWALKW * NBINS; i += NTHREADS) ((int*)sm->histW)[i] = 0;
    if (tid == 0) { sm->tailLen = 0; sm->tailS = 0; }
    if (tid < NWALKW) sm->NvW[tid] = 0;

    // ---- block scan of localSum; write padded cs from registers ----
    {
        int v = localSum;
        #pragma unroll
        for (int d = 1; d < 32; d <<= 1) {
            int n = __shfl_up_sync(0xffffffffu, v, d);
            if (lane >= d) v += n;
        }
        if (lane == 31) sm->wscan[wid] = v;
        __syncthreads();
        if (tid < 16) {
            int wv = sm->wscan[tid];
            #pragma unroll
            for (int d = 1; d < 16; d <<= 1) {
                int n = __shfl_up_sync(0xffffu, wv, d);
                if (tid >= d) wv += n;
            }
            sm->wscan[tid] = wv;
        }
        __syncthreads();
        int base = v - localSum + ((wid > 0) ? sm->wscan[wid - 1] : 0);
        if (tid == 0) sm->cs[0] = 0;
        int run = base;
        #pragma unroll
        for (int k = 0; k < TPT; k++) {
            run += (int)((tw[k >> 2] >> ((k & 3) * 8)) & 0xFF);
            sm->cs[csi(p0 + k + 1)] = (unsigned short)run;   // 18-short stride: conflict-free
        }
    }

    // ---- entropy: packed 4-bit counts, sliding window of 9 ----
    {
        const bool firstT = (tid == 0);
        const bool lastT = (tid == NTHREADS - 1);
        unsigned int pm = 0, ep = 0, ep4 = 0;
        if (!firstT) pm = *(const unsigned int*)(sm->xs + tid * 20 - 8);      // p0-4..p0-1
        if (!lastT) {
            ep  = *(const unsigned int*)(sm->xs + (tid + 1) * 20);            // p0+16..p0+19
            ep4 = sm->xs[(tid + 1) * 20 + 4];                                 // p0+20
        }

        auto tok = [&](int idx) -> unsigned int {
            if (idx < 0)        return (pm >> ((idx + 4) * 8)) & 0xFF;
            else if (idx < TPT) return (tw[idx >> 2] >> ((idx & 3) * 8)) & 0xFF;
            else if (idx < 20)  return (ep >> ((idx - TPT) * 8)) & 0xFF;
            else                return ep4;
        };

        unsigned int packed = 0;
        #pragma unroll
        for (int i = 0; i <= 4; i++) packed += 1u << (tok(i) << 2);
        if (!firstT) {
            #pragma unroll
            for (int i = -4; i < 0; i++) packed += 1u << (tok(i) << 2);
        }

        int r0 = (3 - (p0 % 3)) % 3;
        int q = (p0 + r0) / 3;
        float* entb = sm->ent + tid * 17;     // conflict-free (17-float stride)
        const float* t9 = sm->term9 + lane;

        #pragma unroll
        for (int k = 0; k < TPT; k++) {
            int p = p0 + k;
            float e;
            if ((firstT && k < 4) || (lastT && k >= TPT - 4)) {
                int wl = max(0, p - 4), wh = min(LDIM - 1, p + 4);
                int t = wh - wl + 1;
                const float* tb = sm->term + (t << 4);
                unsigned int pk = packed;
                e  = tb[pk & 15]; pk >>= 4;
                e += tb[pk & 15]; pk >>= 4;
                e += tb[pk & 15]; pk >>= 4;
                e += tb[pk & 15]; pk >>= 4;
                e += tb[pk & 15];
            } else {
                unsigned int pk = packed;
                e  = t9[(pk & 15) << 5]; pk >>= 4;
                e += t9[(pk & 15) << 5]; pk >>= 4;
                e += t9[(pk & 15) << 5]; pk >>= 4;
                e += t9[(pk & 15) << 5]; pk >>= 4;
                e += t9[(pk & 15) << 5];
            }
            entb[k] = e;
            if ((k % 3) == r0) { sm->nxt[q] = (e > 1.5f) ? (unsigned char)1 : (unsigned char)4; q++; }
            if (!(lastT && k >= TPT - 5)) packed += 1u << (tok(k + 5) << 2);
            if (!(firstT && k < 4))       packed -= 1u << (tok(k - 4) << 2);
        }
    }
    __syncthreads();

    // ---- squared step table ----
    for (int p = tid; p < NP; p += NTHREADS) {
        int u = sm->nxt[p];
        int qq = p + u;
        sm->nxt2[p] = (unsigned char)(u + ((qq < NP) ? (int)sm->nxt[qq] : 4));
    }
    __syncthreads();

    // ---- speculative chunk walks: 128 chunks x 4 entries = all 512 threads ----
    {
        int chunk = tid >> 2, e = tid & 3;
        int p = chunk * CH + e;
        int pend = min((chunk + 1) * CH, NP);
        while (p < pend) {
            int u1 = sm->nxt[p];
            int p1 = p + u1;
            if (p1 >= pend) { p = p1; break; }
            p += (int)sm->nxt2[p];
        }
        ((unsigned char*)sm->exitsW)[tid] = (unsigned char)(p - pend);
    }
    __syncthreads();

    // ---- warps 0-3: per-warp map scans || others: entropy copy-out (part 1) ----
    if (tid < NCHUNK) {
        unsigned int m = sm->exitsW[tid];      // chunk = tid
        #pragma unroll
        for (int d = 1; d < 32; d <<= 1) {
            unsigned int pmv = __shfl_up_sync(0xffffffffu, m, d);
            if (lane >= d) {
                unsigned int sel = (pmv & 0x3u) | ((pmv >> 4) & 0x30u) |
                                   ((pmv >> 8) & 0x300u) | ((pmv >> 12) & 0x3000u);
                m = __byte_perm(m, 0, sel);    // m = m_cur ∘ m_prev
            }
        }
        sm->mfull[tid] = m;
        if (lane == 31 && wid < 3) sm->exitsW[NCHUNK - 4 + wid] = m;  // stash warp totals? no:
    } else {
        float* outE = out + (size_t)BDIM * EDIM + (size_t)row * LDIM;
        for (int i = tid - NCHUNK; i < LDIM; i += NTHREADS - NCHUNK) outE[i] = sm->ent[eni(i)];
    }
    __syncthreads();

    // ---- compose warp totals (sequential, 4 steps) ----
    if (tid == 0) {
        unsigned char E = 0;
        sm->wtotE[0] = 0;
        #pragma unroll
        for (int w = 0; w < 3; w++) {
            unsigned int T = sm->mfull[w * 32 + 31];
            E = (unsigned char)((T >> (8 * E)) & 0x3u);
            sm->wtotE[w + 1] = E;
        }
    }
    __syncthreads();

    // ---- per-chunk entry offsets ----
    if (tid < NCHUNK) {
        if (tid == 0) sm->esel[0] = 0;
        if (tid < NCHUNK - 1) {
            unsigned int Ew = sm->wtotE[tid >> 5];
            sm->esel[tid + 1] = (unsigned char)((sm->mfull[tid] >> (8 * Ew)) & 0x3u);
        }
    }
    __syncthreads();

    // ---- real walk: 128 threads, fixed 11 trips, match_any histogram ----
    if (tid < NCHUNK) {
        int p = tid * CH + (int)sm->esel[tid];
        int pend = min((tid + 1) * CH, NP);
        int nv = 0;
        int* hw = sm->histW[wid];
        #pragma unroll 1
        for (int it = 0; it < 11; it++) {
            int key1 = 66, key2 = 66;
            if (p < pend) {
                int u1 = (int)sm->nxt[p];
                int u2 = (int)sm->nxt2[p];
                {
                    int i3 = 3 * p;
                    int j = min(i3 + 3 * u1, LDIM);
                    int len = j - i3;
                    int S = (int)sm->cs[csi(j)] - (int)sm->cs[csi(i3)];
                    nv++;
                    if (len == 3)       key1 = S;
                    else if (len == 12) key1 = 16 + S;
                    else { sm->tailS = S; sm->tailLen = len; }
                }
                int p1 = p + u1;
                if (p1 < pend) {
                    int ul = u2 - u1;
                    int i3 = 3 * p1;
                    int j = min(i3 + 3 * ul, LDIM);
                    int len = j - i3;
                    int S = (int)sm->cs[csi(j)] - (int)sm->cs[csi(i3)];
                    nv++;
                    if (len == 3)       key2 = S;
                    else if (len == 12) key2 = 16 + S;
                    else { sm->tailS = S; sm->tailLen = len; }
                    p += u2;
                } else {
                    p = p1;
                }
            }
            unsigned int g1 = __match_any_sync(0xffffffffu, key1);
            if (key1 != 66 && (__ffs(g1) - 1) == lane) hw[key1] += __popc(g1);
            unsigned int g2 = __match_any_sync(0xffffffffu, key2);
            if (key2 != 66 && (__ffs(g2) - 1) == lane) hw[key2] += __popc(g2);
        }
        #pragma unroll
        for (int d = 16; d > 0; d >>= 1) nv += __shfl_down_sync(0xffffffffu, nv, d);
        if (lane == 0) sm->NvW[wid] = nv;
    } else {
        // stage w2 into padded smem (384 threads)
        for (int i = tid - NCHUNK; i < EDIM * EDIM; i += NTHREADS - NCHUNK) {
            sm->w2s[(i >> 6) * 65 + (i & 63)] = w2[i];
        }
    }
    __syncthreads();

    // ---- hsum[e] = mean over valid patches of relu(mean*w1[e]+b1[e]) via histogram ----
    if (tid < EDIM) {
        float w1e = w1[tid], b1e = b1[tid];
        float acc = 0.0f;
        #pragma unroll
        for (int s = 0; s <= 12; s++) {
            int c = sm->histW[0][s] + sm->histW[1][s] + sm->histW[2][s] + sm->histW[3][s];
            acc += (float)c * fmaxf(fmaf((float)s / 3.0f, w1e, b1e), 0.0f);
        }
        #pragma unroll
        for (int s = 0; s <= 48; s++) {
            int c = sm->histW[0][16 + s] + sm->histW[1][16 + s] +
                    sm->histW[2][16 + s] + sm->histW[3][16 + s];
            acc += (float)c * fmaxf(fmaf((float)s / 12.0f, w1e, b1e), 0.0f);
        }
        if (sm->tailLen > 0)
            acc += fmaxf(fmaf((float)sm->tailS / (float)sm->tailLen, w1e, b1e), 0.0f);
        int Nv = sm->NvW[0] + sm->NvW[1] + sm->NvW[2] + sm->NvW[3];
        sm->hsum[tid] = acc / (float)Nv;
    }
    __syncthreads();

    // ---- vec = hbar @ w2^T + b2 ----
    if (tid < EDIM) {
        const float* wrow = sm->w2s + tid * 65;
        float v = b2[tid];
        #pragma unroll
        for (int e = 0; e < EDIM; e++) v = fmaf(sm->hsum[e], wrow[e], v);
        out[(size_t)row * EDIM + tid] = v;
    }
}

extern "C" void kernel_launch(void* const* d_in, const int* in_sizes, int n_in,
                              void* d_out, int out_size)
{
    const int*   x  = (const int*)d_in[0];
    const float* w1 = (const float*)d_in[1];
    const float* b1 = (const float*)d_in[2];
    const float* w2 = (const float*)d_in[3];
    const float* b2 = (const float*)d_in[4];
    float* out = (float*)d_out;

    cudaFuncSetAttribute(ep_kernel, cudaFuncAttributeMaxDynamicSharedMemorySize,
                         (int)sizeof(SmemLayout));
    ep_kernel<<<BDIM, NTHREADS, sizeof(SmemLayout)>>>(x, w1, b1, w2, b2, out);
}

// round 5
// speedup vs baseline: 2.5943x; 1.0217x over previous
#include <cuda_runtime.h>
#include <math.h>

#define BDIM 256
#define LDIM 8192
#define EDIM 64
#define NP   2731      // patch-start candidates (multiples of 3): ceil(8192/3)
#define NQ   2736      // cs3 entries (q >= 2731 clamped to total)
#define CH   22        // chunk size in p-units (128 chunks cover 2731)
#define NCHUNK 128
#define NTHREADS 512
#define TPT 16         // tokens per thread
#define NBINS 68       // 0..12 len3, 16..64 len12, 66 dummy
#define NWALKW 4

struct SmemLayout {
    float w2s[EDIM * 65];            // 16640 B, padded rows (cp.async filled)
    unsigned short cs3[NQ];          // prefix sums at multiples of 3 (+clamped tail)
    unsigned int nbA[NTHREADS];      // each thread's tw[3] (tokens p0+12..p0+15)
    unsigned int nbB[NTHREADS];      // each thread's tw[0] (tokens p0+0..p0+3)
    unsigned int nbC[NTHREADS];      // token p0+4
    unsigned char nxt[NP + 8];       // step (1 or 4)
    unsigned char nxt2[NP + 8];      // 2-step composition
    unsigned char nxt4[NP + 8];      // 4-step composition
    float term[160];                 // boundary entropy LUT term[t*16+c]
    unsigned int exitsW[NCHUNK];
    unsigned int mfull[NCHUNK];
    unsigned char wtotE[8];
    unsigned char esel[NCHUNK + 4];
    int histW[NWALKW][NBINS];
    int NvW[NWALKW];
    int wscan[16];
    int tailS, tailLen;
    float hsum[EDIM];
};

__global__ void __launch_bounds__(NTHREADS, 2)
ep_kernel(const int* __restrict__ x,
          const float* __restrict__ w1,
          const float* __restrict__ b1,
          const float* __restrict__ w2,
          const float* __restrict__ b2,
          float* __restrict__ out)
{
    extern __shared__ unsigned char raw[];
    SmemLayout* sm = (SmemLayout*)raw;
    const int tid = threadIdx.x;
    const int lane = tid & 31;
    const int wid = tid >> 5;
    const int row = blockIdx.x;
    const int p0 = tid * TPT;

    // ---- stage own 16 tokens into registers; publish neighbor words ----
    const int4* xv = (const int4*)(x + (size_t)row * LDIM) + tid * 4;
    unsigned int tw[4];
    int localSum = 0;
    #pragma unroll
    for (int k = 0; k < 4; k++) {
        int4 v = xv[k];
        unsigned int w = (unsigned int)v.x | ((unsigned int)v.y << 8) |
                         ((unsigned int)v.z << 16) | ((unsigned int)v.w << 24);
        tw[k] = w;
        localSum += v.x + v.y + v.z + v.w;
    }
    sm->nbA[tid] = tw[3];
    sm->nbB[tid] = tw[0];
    sm->nbC[tid] = tw[1] & 0xFF;

    // ---- prefetch w1/b1/b2 into registers (latency hidden across kernel) ----
    float wv1 = 0.0f, bv1 = 0.0f, bv2 = 0.0f;
    if (tid < EDIM) { wv1 = w1[tid]; bv1 = b1[tid]; bv2 = b2[tid]; }

    // ---- w2 -> smem via cp.async (4B), fire-and-forget ----
    {
        #pragma unroll
        for (int r = 0; r < 8; r++) {
            int i = tid + r * NTHREADS;
            unsigned int dst = (unsigned int)__cvta_generic_to_shared(
                &sm->w2s[(i >> 6) * 65 + (i & 63)]);
            const float* src = w2 + i;
            asm volatile("cp.async.ca.shared.global [%0], [%1], 4;\n"
                         :: "r"(dst), "l"(src));
        }
        asm volatile("cp.async.commit_group;\n" ::: "memory");
    }

    // ---- per-lane shuffle LUT value: term9[lane] ----
    float tval;
    {
        float pv = (float)lane / 9.0f;
        tval = (lane <= 9) ? -(pv * log2f(pv + 1e-12f)) : 0.0f;
    }

    // ---- boundary LUT & init ----
    if (tid < 160) {
        int t = tid >> 4, c = tid & 15;
        float v = 0.0f;
        if (t >= 1 && c <= t) { float pv = (float)c / (float)t; v = -(pv * log2f(pv + 1e-12f)); }
        sm->term[tid] = v;
    }
    for (int i = tid; i < NWALKW * NBINS; i += NTHREADS) ((int*)sm->histW)[i] = 0;
    if (tid == 0) { sm->tailLen = 0; sm->tailS = 0; }
    if (tid < NWALKW) sm->NvW[tid] = 0;
    __syncthreads();

    // ---- block scan of localSum; write cs3 (multiples of 3 only) ----
    {
        int v = localSum;
        #pragma unroll
        for (int d = 1; d < 32; d <<= 1) {
            int n = __shfl_up_sync(0xffffffffu, v, d);
            if (lane >= d) v += n;
        }
        if (lane == 31) sm->wscan[wid] = v;
        __syncthreads();
        if (tid < 16) {
            int wv = sm->wscan[tid];
            #pragma unroll
            for (int d = 1; d < 16; d <<= 1) {
                int n = __shfl_up_sync(0xffffu, wv, d);
                if (tid >= d) wv += n;
            }
            sm->wscan[tid] = wv;
        }
        __syncthreads();
        int base = v - localSum + ((wid > 0) ? sm->wscan[wid - 1] : 0);
        if (tid == 0) sm->cs3[0] = 0;
        int run = base;
        #pragma unroll
        for (int k = 0; k < TPT; k++) {
            run += (int)((tw[k >> 2] >> ((k & 3) * 8)) & 0xFF);
            int idx = p0 + k + 1;
            if (idx % 3 == 0) sm->cs3[idx / 3] = (unsigned short)run;
        }
        if (tid == NTHREADS - 1) {   // run == total == cs[8192]
            #pragma unroll
            for (int q = NP; q < NQ; q++) sm->cs3[q] = (unsigned short)run;
        }
    }

    // ---- entropy: packed 4-bit counts, window 9, shuffle LUT, direct STG ----
    {
        const bool firstT = (tid == 0);
        const bool lastT = (tid == NTHREADS - 1);
        unsigned int pm = firstT ? 0u : sm->nbA[tid - 1];     // tokens p0-4..p0-1
        unsigned int ep = lastT ? 0u : sm->nbB[tid + 1];      // tokens p0+16..p0+19
        unsigned int ep4 = lastT ? 0u : sm->nbC[tid + 1];     // token p0+20

        auto tok = [&](int idx) -> unsigned int {
            if (idx < 0)        return (pm >> ((idx + 4) * 8)) & 0xFF;
            else if (idx < TPT) return (tw[idx >> 2] >> ((idx & 3) * 8)) & 0xFF;
            else if (idx < 20)  return (ep >> ((idx - TPT) * 8)) & 0xFF;
            else                return ep4;
        };

        unsigned int packed = 0;
        #pragma unroll
        for (int i = 0; i <= 4; i++) packed += 1u << (tok(i) << 2);
        if (!firstT) {
            #pragma unroll
            for (int i = -4; i < 0; i++) packed += 1u << (tok(i) << 2);
        }

        int r0 = (3 - (p0 % 3)) % 3;
        int q = (p0 + r0) / 3;
        float4* outE4 = (float4*)(out + (size_t)BDIM * EDIM + (size_t)row * LDIM + p0);
        float4 stage;

        #pragma unroll
        for (int k = 0; k < TPT; k++) {
            int p = p0 + k;
            // uniform shuffle-LUT path (all lanes participate)
            unsigned int pk = packed;
            float e = __shfl_sync(0xffffffffu, tval, (int)(pk & 15)); pk >>= 4;
            e += __shfl_sync(0xffffffffu, tval, (int)(pk & 15)); pk >>= 4;
            e += __shfl_sync(0xffffffffu, tval, (int)(pk & 15)); pk >>= 4;
            e += __shfl_sync(0xffffffffu, tval, (int)(pk & 15)); pk >>= 4;
            e += __shfl_sync(0xffffffffu, tval, (int)(pk & 15));
            // boundary override (no shuffles inside — divergence safe)
            if ((firstT && k < 4) || (lastT && k >= TPT - 4)) {
                int wl = max(0, p - 4), wh = min(LDIM - 1, p + 4);
                int t = wh - wl + 1;
                const float* tb = sm->term + (t << 4);
                unsigned int pk2 = packed;
                e  = tb[pk2 & 15]; pk2 >>= 4;
                e += tb[pk2 & 15]; pk2 >>= 4;
                e += tb[pk2 & 15]; pk2 >>= 4;
                e += tb[pk2 & 15]; pk2 >>= 4;
                e += tb[pk2 & 15];
            }
            if ((k & 3) == 0) stage.x = e;
            else if ((k & 3) == 1) stage.y = e;
            else if ((k & 3) == 2) stage.z = e;
            else { stage.w = e; outE4[k >> 2] = stage; }
            if ((k % 3) == r0) { sm->nxt[q] = (e > 1.5f) ? (unsigned char)1 : (unsigned char)4; q++; }
            if (!(lastT && k >= TPT - 5)) packed += 1u << (tok(k + 5) << 2);
            if (!(firstT && k < 4))       packed -= 1u << (tok(k - 4) << 2);
        }
    }
    __syncthreads();

    // ---- nxt2 ----
    for (int p = tid; p < NP; p += NTHREADS) {
        int u = sm->nxt[p];
        int qq = p + u;
        sm->nxt2[p] = (unsigned char)(u + ((qq < NP) ? (int)sm->nxt[qq] : 4));
    }
    __syncthreads();

    // ---- nxt4 ----
    for (int p = tid; p < NP; p += NTHREADS) {
        int u2 = sm->nxt2[p];
        int q2 = p + u2;
        sm->nxt4[p] = (unsigned char)(u2 + ((q2 < NP) ? (int)sm->nxt2[q2] : 8));
    }
    __syncthreads();

    // ---- speculative chunk walks: 128 chunks x 4 entries = all 512 threads ----
    {
        int chunk = tid >> 2, e = tid & 3;
        int p = chunk * CH + e;
        int pend = min((chunk + 1) * CH, NP);
        while (p + (int)sm->nxt4[p] < pend) p += (int)sm->nxt4[p];
        if (p < pend) {
            int u2 = (int)sm->nxt2[p];
            if (p + u2 < pend) p += u2;
            while (p < pend) p += (int)sm->nxt[p];
        }
        ((unsigned char*)sm->exitsW)[tid] = (unsigned char)(p - pend);
    }
    __syncthreads();

    // ---- warps 0-3: per-warp map scans ----
    if (tid < NCHUNK) {
        unsigned int m = sm->exitsW[tid];
        #pragma unroll
        for (int d = 1; d < 32; d <<= 1) {
            unsigned int pmv = __shfl_up_sync(0xffffffffu, m, d);
            if (lane >= d) {
                unsigned int sel = (pmv & 0x3u) | ((pmv >> 4) & 0x30u) |
                                   ((pmv >> 8) & 0x300u) | ((pmv >> 12) & 0x3000u);
                m = __byte_perm(m, 0, sel);    // m = m_cur ∘ m_prev
            }
        }
        sm->mfull[tid] = m;
    }
    __syncthreads();

    // ---- compose warp totals ----
    if (tid == 0) {
        unsigned char E = 0;
        sm->wtotE[0] = 0;
        #pragma unroll
        for (int w = 0; w < 3; w++) {
            unsigned int T = sm->mfull[w * 32 + 31];
            E = (unsigned char)((T >> (8 * E)) & 0x3u);
            sm->wtotE[w + 1] = E;
        }
    }
    __syncthreads();

    // ---- per-chunk entry offsets ----
    if (tid < NCHUNK) {
        if (tid == 0) sm->esel[0] = 0;
        if (tid < NCHUNK - 1) {
            unsigned int Ew = sm->wtotE[tid >> 5];
            sm->esel[tid + 1] = (unsigned char)((sm->mfull[tid] >> (8 * Ew)) & 0x3u);
        }
    }
    __syncthreads();

    // ---- real walk: 128 threads, 6 fixed trips, 4 patches/trip, match_any hist ----
    if (tid < NCHUNK) {
        int p = tid * CH + (int)sm->esel[tid];
        int pend = min((tid + 1) * CH, NP);
        int nv = 0;
        int* hw = sm->histW[wid];

        #pragma unroll 1
        for (int it = 0; it < 6; it++) {
            int key0 = 66, key1 = 66, key2 = 66, key3 = 66;
            if (p < pend) {
                int u1 = (int)sm->nxt[p];
                int u2 = (int)sm->nxt2[p];
                {   // patch 0: [p, p+u1)
                    int qn = p + u1;
                    int j = min(3 * qn, LDIM);
                    int len = j - 3 * p;
                    int S = (int)sm->cs3[qn] - (int)sm->cs3[p];
                    nv++;
                    if (len == 3) key0 = S; else if (len == 12) key0 = 16 + S;
                    else { sm->tailS = S; sm->tailLen = len; }
                }
                int p1 = p + u1;
                if (p1 < pend) {
                    int ul = u2 - u1;
                    int qn = p1 + ul;
                    int j = min(3 * qn, LDIM);
                    int len = j - 3 * p1;
                    int S = (int)sm->cs3[qn] - (int)sm->cs3[p1];
                    nv++;
                    if (len == 3) key1 = S; else if (len == 12) key1 = 16 + S;
                    else { sm->tailS = S; sm->tailLen = len; }
                    int p2 = p + u2;
                    if (p2 < pend) {
                        int u3 = (int)sm->nxt[p2];
                        int u4 = (int)sm->nxt2[p2];
                        {   // patch 2
                            int qn2 = p2 + u3;
                            int j2 = min(3 * qn2, LDIM);
                            int len2 = j2 - 3 * p2;
                            int S2 = (int)sm->cs3[qn2] - (int)sm->cs3[p2];
                            nv++;
                            if (len2 == 3) key2 = S2; else if (len2 == 12) key2 = 16 + S2;
                            else { sm->tailS = S2; sm->tailLen = len2; }
                        }
                        int p3 = p2 + u3;
                        if (p3 < pend) {
                            int ul2 = u4 - u3;
                            int qn3 = p3 + ul2;
                            int j3 = min(3 * qn3, LDIM);
                            int len3 = j3 - 3 * p3;
                            int S3 = (int)sm->cs3[qn3] - (int)sm->cs3[p3];
                            nv++;
                            if (len3 == 3) key3 = S3; else if (len3 == 12) key3 = 16 + S3;
                            else { sm->tailS = S3; sm->tailLen = len3; }
                            p = p2 + u4;
                        } else p = p3;
                    } else p = p2;
                } else p = p1;
            }
            unsigned int g;
            g = __match_any_sync(0xffffffffu, key0);
            if (key0 != 66 && (__ffs(g) - 1) == lane) hw[key0] += __popc(g);
            g = __match_any_sync(0xffffffffu, key1);
            if (key1 != 66 && (__ffs(g) - 1) == lane) hw[key1] += __popc(g);
            g = __match_any_sync(0xffffffffu, key2);
            if (key2 != 66 && (__ffs(g) - 1) == lane) hw[key2] += __popc(g);
            g = __match_any_sync(0xffffffffu, key3);
            if (key3 != 66 && (__ffs(g) - 1) == lane) hw[key3] += __popc(g);
        }
        #pragma unroll
        for (int d = 16; d > 0; d >>= 1) nv += __shfl_down_sync(0xffffffffu, nv, d);
        if (lane == 0) sm->NvW[wid] = nv;
    }
    asm volatile("cp.async.wait_group 0;\n" ::: "memory");
    __syncthreads();

    // ---- hsum[e] = mean over valid patches of relu(mean*w1[e]+b1[e]) ----
    if (tid < EDIM) {
        float acc = 0.0f;
        #pragma unroll
        for (int s = 0; s <= 12; s++) {
            int c = sm->histW[0][s] + sm->histW[1][s] + sm->histW[2][s] + sm->histW[3][s];
            acc += (float)c * fmaxf(fmaf((float)s / 3.0f, wv1, bv1), 0.0f);
        }
        #pragma unroll
        for (int s = 0; s <= 48; s++) {
            int c = sm->histW[0][16 + s] + sm->histW[1][16 + s] +
                    sm->histW[2][16 + s] + sm->histW[3][16 + s];
            acc += (float)c * fmaxf(fmaf((float)s / 12.0f, wv1, bv1), 0.0f);
        }
        if (sm->tailLen > 0)
            acc += fmaxf(fmaf((float)sm->tailS / (float)sm->tailLen, wv1, bv1), 0.0f);
        int Nv = sm->NvW[0] + sm->NvW[1] + sm->NvW[2] + sm->NvW[3];
        sm->hsum[tid] = acc / (float)Nv;
    }
    __syncthreads();

    // ---- vec = hbar @ w2^T + b2 ----
    if (tid < EDIM) {
        const float* wrow = sm->w2s + tid * 65;
        float v = bv2;
        #pragma unroll
        for (int e = 0; e < EDIM; e++) v = fmaf(sm->hsum[e], wrow[e], v);
        out[(size_t)row * EDIM + tid] = v;
    }
}

extern "C" void kernel_launch(void* const* d_in, const int* in_sizes, int n_in,
                              void* d_out, int out_size)
{
    const int*   x  = (const int*)d_in[0];
    const float* w1 = (const float*)d_in[1];
    const float* b1 = (const float*)d_in[2];
    const float* w2 = (const float*)d_in[3];
    const float* b2 = (const float*)d_in[4];
    float* out = (float*)d_out;

    cudaFuncSetAttribute(ep_kernel, cudaFuncAttributeMaxDynamicSharedMemorySize,
                         (int)sizeof(SmemLayout));
    ep_kernel<<<BDIM, NTHREADS, sizeof(SmemLayout)>>>(x, w1, b1, w2, b2, out);
}

// round 6
// speedup vs baseline: 2.6250x; 1.0118x over previous
#include <cuda_runtime.h>
#include <math.h>

#define BDIM 256
#define LDIM 8192
#define EDIM 64
#define NP   2731      // patch-start candidates (multiples of 3): ceil(8192/3)
#define NQ   2736      // cs3 entries (q >= 2731 clamped to total)
#define CH   22        // chunk size in p-units (128 chunks cover 2731)
#define NCHUNK 128
#define NTHREADS 512
#define TPT 16         // tokens per thread
#define NBINS 68       // 0..12 len3, 16..64 len12, 66 dummy
#define NWALKW 4
#define LOG2_9 3.169925001442312f

struct SmemLayout {
    float w2s[EDIM * 65];            // padded rows (cp.async filled)
    unsigned short cs3[NQ];          // prefix sums at multiples of 3 (+clamped tail)
    unsigned int nbA[NTHREADS];      // each thread's tw[3]
    unsigned int nbB[NTHREADS];      // each thread's tw[0]
    unsigned int nbC[NTHREADS];      // token p0+4
    unsigned char nxt[NP + 8];       // step (1 or 4)
    unsigned char nxt2[NP + 8];
    unsigned char nxt4[NP + 8];
    float term[160];                 // boundary entropy LUT term[t*16+c] (bit-exact ref path)
    float clrep[12 * 32];            // c*log2(c), replicated per lane
    float dlrep[12 * 32];            // cl[c]-cl[c-1], replicated per lane
    unsigned int exitsW[NCHUNK];
    unsigned int mfull[NCHUNK];
    unsigned char wtotE[8];
    unsigned char esel[NCHUNK + 4];
    int histW[NWALKW][NBINS];
    int NvW[NWALKW];
    int wscan[16];
    int tailS, tailLen;
    float hsum[EDIM];
};

__global__ void __launch_bounds__(NTHREADS, 2)
ep_kernel(const int* __restrict__ x,
          const float* __restrict__ w1,
          const float* __restrict__ b1,
          const float* __restrict__ w2,
          const float* __restrict__ b2,
          float* __restrict__ out)
{
    extern __shared__ unsigned char raw[];
    SmemLayout* sm = (SmemLayout*)raw;
    const int tid = threadIdx.x;
    const int lane = tid & 31;
    const int wid = tid >> 5;
    const int row = blockIdx.x;
    const int p0 = tid * TPT;

    // ---- stage own 16 tokens into registers; publish neighbor words ----
    const int4* xv = (const int4*)(x + (size_t)row * LDIM) + tid * 4;
    unsigned int tw[4];
    int localSum = 0;
    #pragma unroll
    for (int k = 0; k < 4; k++) {
        int4 v = xv[k];
        unsigned int w = (unsigned int)v.x | ((unsigned int)v.y << 8) |
                         ((unsigned int)v.z << 16) | ((unsigned int)v.w << 24);
        tw[k] = w;
        localSum += v.x + v.y + v.z + v.w;
    }
    sm->nbA[tid] = tw[3];
    sm->nbB[tid] = tw[0];
    sm->nbC[tid] = tw[1] & 0xFF;

    // ---- prefetch w1/b1/b2 into registers ----
    float wv1 = 0.0f, bv1 = 0.0f, bv2 = 0.0f;
    if (tid < EDIM) { wv1 = w1[tid]; bv1 = b1[tid]; bv2 = b2[tid]; }

    // ---- w2 -> smem via cp.async, fire-and-forget ----
    {
        #pragma unroll
        for (int r = 0; r < 8; r++) {
            int i = tid + r * NTHREADS;
            unsigned int dst = (unsigned int)__cvta_generic_to_shared(
                &sm->w2s[(i >> 6) * 65 + (i & 63)]);
            const float* src = w2 + i;
            asm volatile("cp.async.ca.shared.global [%0], [%1], 4;\n"
                         :: "r"(dst), "l"(src));
        }
        asm volatile("cp.async.commit_group;\n" ::: "memory");
    }

    // ---- LUTs & init ----
    if (tid < 160) {
        int t = tid >> 4, c = tid & 15;
        float v = 0.0f;
        if (t >= 1 && c <= t) { float pv = (float)c / (float)t; v = -(pv * log2f(pv + 1e-12f)); }
        sm->term[tid] = v;
    }
    if (tid >= 160 && tid < 160 + 384) {
        int i = tid - 160;
        int c = i >> 5;
        float cl  = (c >= 1 && c <= 10) ? (float)c * log2f((float)c) : 0.0f;
        float clm = (c >= 2 && c <= 10) ? (float)(c - 1) * log2f((float)(c - 1)) : 0.0f;
        sm->clrep[i] = cl;
        sm->dlrep[i] = (c >= 1 && c <= 10) ? (cl - clm) : 0.0f;
    }
    for (int i = tid; i < NWALKW * NBINS; i += NTHREADS) ((int*)sm->histW)[i] = 0;
    if (tid == 0) { sm->tailLen = 0; sm->tailS = 0; }
    if (tid < NWALKW) sm->NvW[tid] = 0;
    __syncthreads();

    // ---- block scan of localSum; write cs3 (multiples of 3 only) ----
    {
        int v = localSum;
        #pragma unroll
        for (int d = 1; d < 32; d <<= 1) {
            int n = __shfl_up_sync(0xffffffffu, v, d);
            if (lane >= d) v += n;
        }
        if (lane == 31) sm->wscan[wid] = v;
        __syncthreads();
        if (tid < 16) {
            int wv = sm->wscan[tid];
            #pragma unroll
            for (int d = 1; d < 16; d <<= 1) {
                int n = __shfl_up_sync(0xffffu, wv, d);
                if (tid >= d) wv += n;
            }
            sm->wscan[tid] = wv;
        }
        __syncthreads();
        int base = v - localSum + ((wid > 0) ? sm->wscan[wid - 1] : 0);
        if (tid == 0) sm->cs3[0] = 0;
        int run = base;
        #pragma unroll
        for (int k = 0; k < TPT; k++) {
            run += (int)((tw[k >> 2] >> ((k & 3) * 8)) & 0xFF);
            int idx = p0 + k + 1;
            if (idx % 3 == 0) sm->cs3[idx / 3] = (unsigned short)run;
        }
        if (tid == NTHREADS - 1) {
            #pragma unroll
            for (int q = NP; q < NQ; q++) sm->cs3[q] = (unsigned short)run;
        }
    }

    // ---- entropy: incremental S = sum(c*log2 c), 2 LDS per position ----
    {
        const bool firstT = (tid == 0);
        const bool lastT = (tid == NTHREADS - 1);
        unsigned int pm = firstT ? 0u : sm->nbA[tid - 1];     // tokens p0-4..p0-1
        unsigned int ep = lastT ? 0u : sm->nbB[tid + 1];      // tokens p0+16..p0+19
        unsigned int ep4 = lastT ? 0u : sm->nbC[tid + 1];     // token p0+20

        auto tok = [&](int idx) -> unsigned int {
            if (idx < 0)        return (pm >> ((idx + 4) * 8)) & 0xFF;
            else if (idx < TPT) return (tw[idx >> 2] >> ((idx & 3) * 8)) & 0xFF;
            else if (idx < 20)  return (ep >> ((idx - TPT) * 8)) & 0xFF;
            else                return ep4;
        };

        unsigned int packed = 0;
        #pragma unroll
        for (int i = 0; i <= 4; i++) packed += 1u << (tok(i) << 2);
        if (!firstT) {
            #pragma unroll
            for (int i = -4; i < 0; i++) packed += 1u << (tok(i) << 2);
        }

        const float* cl_lane = sm->clrep + lane;
        const float* dl_lane = sm->dlrep + lane;

        // initial S from packed counts
        float S = 0.0f;
        {
            unsigned int pk = packed;
            #pragma unroll
            for (int c5 = 0; c5 < 5; c5++) { S += cl_lane[(pk & 15u) << 5]; pk >>= 4; }
        }

        int r0 = (3 - (p0 % 3)) % 3;
        int q = (p0 + r0) / 3;
        float4* outE4 = (float4*)(out + (size_t)BDIM * EDIM + (size_t)row * LDIM + p0);
        float4 stage;

        #pragma unroll
        for (int k = 0; k < TPT; k++) {
            // interior entropy from running S (t = 9)
            float e = fmaf(-(1.0f / 9.0f), S, LOG2_9);
            // boundary override: bit-exact reference-term path (threads 0/511 only)
            if ((firstT && k < 4) || (lastT && k >= TPT - 4)) {
                int p = p0 + k;
                int wl = max(0, p - 4), wh = min(LDIM - 1, p + 4);
                int t = wh - wl + 1;
                const float* tb = sm->term + (t << 4);
                unsigned int pk2 = packed;
                e  = tb[pk2 & 15]; pk2 >>= 4;
                e += tb[pk2 & 15]; pk2 >>= 4;
                e += tb[pk2 & 15]; pk2 >>= 4;
                e += tb[pk2 & 15]; pk2 >>= 4;
                e += tb[pk2 & 15];
            }
            if ((k & 3) == 0) stage.x = e;
            else if ((k & 3) == 1) stage.y = e;
            else if ((k & 3) == 2) stage.z = e;
            else { stage.w = e; outE4[k >> 2] = stage; }
            if ((k % 3) == r0) { sm->nxt[q] = (e > 1.5f) ? (unsigned char)1 : (unsigned char)4; q++; }

            // slide: remove token p-4 first (counts stay <= 9), then add token p+5
            if (!(firstT && k < 4)) {
                unsigned int b = tok(k - 4);
                unsigned int sh = b << 2;
                unsigned int cb = (packed >> sh) & 15u;
                S -= dl_lane[cb << 5];
                packed -= 1u << sh;
            }
            if (!(lastT && k >= TPT - 5)) {
                unsigned int a = tok(k + 5);
                unsigned int sh = a << 2;
                unsigned int ca = (packed >> sh) & 15u;
                S += dl_lane[(ca + 1u) << 5];
                packed += 1u << sh;
            }
        }
    }
    __syncthreads();

    // ---- nxt2 ----
    for (int p = tid; p < NP; p += NTHREADS) {
        int u = sm->nxt[p];
        int qq = p + u;
        sm->nxt2[p] = (unsigned char)(u + ((qq < NP) ? (int)sm->nxt[qq] : 4));
    }
    __syncthreads();

    // ---- nxt4 ----
    for (int p = tid; p < NP; p += NTHREADS) {
        int u2 = sm->nxt2[p];
        int q2 = p + u2;
        sm->nxt4[p] = (unsigned char)(u2 + ((q2 < NP) ? (int)sm->nxt2[q2] : 8));
    }
    __syncthreads();

    // ---- speculative chunk walks: 128 chunks x 4 entries = all 512 threads ----
    {
        int chunk = tid >> 2, e = tid & 3;
        int p = chunk * CH + e;
        int pend = min((chunk + 1) * CH, NP);
        while (p + (int)sm->nxt4[p] < pend) p += (int)sm->nxt4[p];
        if (p < pend) {
            int u2 = (int)sm->nxt2[p];
            if (p + u2 < pend) p += u2;
            while (p < pend) p += (int)sm->nxt[p];
        }
        ((unsigned char*)sm->exitsW)[tid] = (unsigned char)(p - pend);
    }
    __syncthreads();

    // ---- warps 0-3: per-warp map scans ----
    if (tid < NCHUNK) {
        unsigned int m = sm->exitsW[tid];
        #pragma unroll
        for (int d = 1; d < 32; d <<= 1) {
            unsigned int pmv = __shfl_up_sync(0xffffffffu, m, d);
            if (lane >= d) {
                unsigned int sel = (pmv & 0x3u) | ((pmv >> 4) & 0x30u) |
                                   ((pmv >> 8) & 0x300u) | ((pmv >> 12) & 0x3000u);
                m = __byte_perm(m, 0, sel);
            }
        }
        sm->mfull[tid] = m;
    }
    __syncthreads();

    // ---- compose warp totals ----
    if (tid == 0) {
        unsigned char E = 0;
        sm->wtotE[0] = 0;
        #pragma unroll
        for (int w = 0; w < 3; w++) {
            unsigned int T = sm->mfull[w * 32 + 31];
            E = (unsigned char)((T >> (8 * E)) & 0x3u);
            sm->wtotE[w + 1] = E;
        }
    }
    __syncthreads();

    // ---- per-chunk entry offsets ----
    if (tid < NCHUNK) {
        if (tid == 0) sm->esel[0] = 0;
        if (tid < NCHUNK - 1) {
            unsigned int Ew = sm->wtotE[tid >> 5];
            sm->esel[tid + 1] = (unsigned char)((sm->mfull[tid] >> (8 * Ew)) & 0x3u);
        }
    }
    __syncthreads();

    // ---- real walk: 128 threads, 6 fixed trips, 4 patches/trip, match_any hist ----
    if (tid < NCHUNK) {
        int p = tid * CH + (int)sm->esel[tid];
        int pend = min((tid + 1) * CH, NP);
        int nv = 0;
        int* hw = sm->histW[wid];

        #pragma unroll 1
        for (int it = 0; it < 6; it++) {
            int key0 = 66, key1 = 66, key2 = 66, key3 = 66;
            if (p < pend) {
                int u1 = (int)sm->nxt[p];
                int u2 = (int)sm->nxt2[p];
                {
                    int qn = p + u1;
                    int j = min(3 * qn, LDIM);
                    int len = j - 3 * p;
                    int S = (int)sm->cs3[qn] - (int)sm->cs3[p];
                    nv++;
                    if (len == 3) key0 = S; else if (len == 12) key0 = 16 + S;
                    else { sm->tailS = S; sm->tailLen = len; }
                }
                int p1 = p + u1;
                if (p1 < pend) {
                    int ul = u2 - u1;
                    int qn = p1 + ul;
                    int j = min(3 * qn, LDIM);
                    int len = j - 3 * p1;
                    int S = (int)sm->cs3[qn] - (int)sm->cs3[p1];
                    nv++;
                    if (len == 3) key1 = S; else if (len == 12) key1 = 16 + S;
                    else { sm->tailS = S; sm->tailLen = len; }
                    int p2 = p + u2;
                    if (p2 < pend) {
                        int u3 = (int)sm->nxt[p2];
                        int u4 = (int)sm->nxt2[p2];
                        {
                            int qn2 = p2 + u3;
                            int j2 = min(3 * qn2, LDIM);
                            int len2 = j2 - 3 * p2;
                            int S2 = (int)sm->cs3[qn2] - (int)sm->cs3[p2];
                            nv++;
                            if (len2 == 3) key2 = S2; else if (len2 == 12) key2 = 16 + S2;
                            else { sm->tailS = S2; sm->tailLen = len2; }
                        }
                        int p3 = p2 + u3;
                        if (p3 < pend) {
                            int ul2 = u4 - u3;
                            int qn3 = p3 + ul2;
                            int j3 = min(3 * qn3, LDIM);
                            int len3 = j3 - 3 * p3;
                            int S3 = (int)sm->cs3[qn3] - (int)sm->cs3[p3];
                            nv++;
                            if (len3 == 3) key3 = S3; else if (len3 == 12) key3 = 16 + S3;
                            else { sm->tailS = S3; sm->tailLen = len3; }
                            p = p2 + u4;
                        } else p = p3;
                    } else p = p2;
                } else p = p1;
            }
            unsigned int g;
            g = __match_any_sync(0xffffffffu, key0);
            if (key0 != 66 && (__ffs(g) - 1) == lane) hw[key0] += __popc(g);
            g = __match_any_sync(0xffffffffu, key1);
            if (key1 != 66 && (__ffs(g) - 1) == lane) hw[key1] += __popc(g);
            g = __match_any_sync(0xffffffffu, key2);
            if (key2 != 66 && (__ffs(g) - 1) == lane) hw[key2] += __popc(g);
            g = __match_any_sync(0xffffffffu, key3);
            if (key3 != 66 && (__ffs(g) - 1) == lane) hw[key3] += __popc(g);
        }
        #pragma unroll
        for (int d = 16; d > 0; d >>= 1) nv += __shfl_down_sync(0xffffffffu, nv, d);
        if (lane == 0) sm->NvW[wid] = nv;
    }
    asm volatile("cp.async.wait_group 0;\n" ::: "memory");
    __syncthreads();

    // ---- merge per-warp histograms into histW[0] ----
    if (tid < NBINS) {
        sm->histW[0][tid] += sm->histW[1][tid] + sm->histW[2][tid] + sm->histW[3][tid];
    }
    __syncthreads();

    // ---- hsum[e] = mean over valid patches of relu(mean*w1[e]+b1[e]) ----
    if (tid < EDIM) {
        float acc = 0.0f;
        #pragma unroll
        for (int s = 0; s <= 12; s++) {
            int c = sm->histW[0][s];
            acc += (float)c * fmaxf(fmaf((float)s / 3.0f, wv1, bv1), 0.0f);
        }
        #pragma unroll
        for (int s = 0; s <= 48; s++) {
            int c = sm->histW[0][16 + s];
            acc += (float)c * fmaxf(fmaf((float)s / 12.0f, wv1, bv1), 0.0f);
        }
        if (sm->tailLen > 0)
            acc += fmaxf(fmaf((float)sm->tailS / (float)sm->tailLen, wv1, bv1), 0.0f);
        int Nv = sm->NvW[0] + sm->NvW[1] + sm->NvW[2] + sm->NvW[3];
        sm->hsum[tid] = acc / (float)Nv;
    }
    __syncthreads();

    // ---- vec = hbar @ w2^T + b2 ----
    if (tid < EDIM) {
        const float* wrow = sm->w2s + tid * 65;
        float v = bv2;
        #pragma unroll
        for (int e = 0; e < EDIM; e++) v = fmaf(sm->hsum[e], wrow[e], v);
        out[(size_t)row * EDIM + tid] = v;
    }
}

extern "C" void kernel_launch(void* const* d_in, const int* in_sizes, int n_in,
                              void* d_out, int out_size)
{
    const int*   x  = (const int*)d_in[0];
    const float* w1 = (const float*)d_in[1];
    const float* b1 = (const float*)d_in[2];
    const float* w2 = (const float*)d_in[3];
    const float* b2 = (const float*)d_in[4];
    float* out = (float*)d_out;

    cudaFuncSetAttribute(ep_kernel, cudaFuncAttributeMaxDynamicSharedMemorySize,
                         (int)sizeof(SmemLayout));
    ep_kernel<<<BDIM, NTHREADS, sizeof(SmemLayout)>>>(x, w1, b1, w2, b2, out);
}